// round 2
// baseline (speedup 1.0000x reference)
#include <cuda_runtime.h>
#include <cuda_bf16.h>

#define NX 1024
#define NY 1024
#define EPSV 1e-10f
#define BLOCK_T 256
#define PTS_PER_THREAD 8   // eval: 8 consecutive points per thread

// Scratch (allocation-free rule: __device__ globals)
__device__ float  g_gx[NX];
__device__ float  g_gy[NY];
// Packed 2x2 stencil: g_quad[ix*1024 + iy] = {u00, u10, u01, u11}
__device__ float4 g_quad[(NX - 1) * NY];

// ---------------------------------------------------------------------------
// Fused builder: blocks 0..1022 pack one quad row each; blocks 1023/1024
// build the x / y adaptive grids with a 256-thread shfl scan (low latency,
// hidden under the quad rows' memory traffic).
// ---------------------------------------------------------------------------
__device__ __forceinline__ void build_one_grid(const float* __restrict__ inc,
                                               float* __restrict__ g) {
    __shared__ float scum[1024];
    __shared__ float swarp[8];

    const int t    = threadIdx.x;       // 0..255
    const int lane = t & 31;
    const int warp = t >> 5;

    // Each thread handles 4 elements: j = 4t..4t+3 (element 1023 padded to 0)
    float v[4];
    #pragma unroll
    for (int j = 0; j < 4; j++) {
        int idx = 4 * t + j;
        float val = 0.0f;
        if (idx < 1023) {
            float xv = inc[idx];
            float sp = fmaxf(xv, 0.0f) + log1pf(expf(-fabsf(xv)));  // softplus
            val = fmaxf(sp, 1e-6f);
        }
        v[j] = val;
    }
    // thread-local inclusive
    float c0 = v[0];
    float c1 = c0 + v[1];
    float c2 = c1 + v[2];
    float c3 = c2 + v[3];

    // warp inclusive scan of per-thread totals
    float incl = c3;
    #pragma unroll
    for (int off = 1; off < 32; off <<= 1) {
        float up = __shfl_up_sync(0xffffffff, incl, off);
        if (lane >= off) incl += up;
    }
    float thr_excl = incl - c3;
    if (lane == 31) swarp[warp] = incl;   // warp total
    __syncthreads();

    // scan 8 warp totals (single warp)
    if (warp == 0 && lane < 8) {
        float w = swarp[lane];
        #pragma unroll
        for (int off = 1; off < 8; off <<= 1) {
            float up = __shfl_up_sync(0xff, w, off);
            if (lane >= off) w += up;
        }
        swarp[lane] = w - swarp[lane];    // exclusive warp offset
    }
    __syncthreads();

    float pref = swarp[warp] + thr_excl;
    scum[4 * t + 0] = pref + c0;
    scum[4 * t + 1] = pref + c1;
    scum[4 * t + 2] = pref + c2;
    scum[4 * t + 3] = pref + c3;
    __syncthreads();

    float total = scum[1022];             // cum[-1]
    if (t == 0) g[0] = 0.0f;
    #pragma unroll
    for (int j = 0; j < 4; j++) {
        int idx = 4 * t + j;
        if (idx < 1022)       g[idx + 1] = scum[idx] / total;
        else if (idx == 1022) g[1023]    = 1.0f;
    }
}

__global__ __launch_bounds__(BLOCK_T)
void build_all(const float* __restrict__ incx,
               const float* __restrict__ incy,
               const float* __restrict__ u) {
    int bx = blockIdx.x;
    if (bx < NX - 1) {
        // quad row bx
        const float* r0 = u + bx * NY;
        const float* r1 = r0 + NY;
        float4* qrow = g_quad + (bx << 10);
        for (int iy = threadIdx.x; iy < NY - 1; iy += BLOCK_T) {
            float4 q;
            q.x = r0[iy];
            q.y = r1[iy];
            q.z = r0[iy + 1];
            q.w = r1[iy + 1];
            qrow[iy] = q;
        }
    } else if (bx == NX - 1) {
        build_one_grid(incx, g_gx);
    } else {
        build_one_grid(incy, g_gy);
    }
}

// ---------------------------------------------------------------------------
// Eval
// ---------------------------------------------------------------------------
__device__ __forceinline__ int find_cell(float x, const float* __restrict__ sg) {
    int ix = min(max(__float2int_rd(x * 1023.0f), 0), NX - 2);
    while (ix > 0 && sg[ix] >= x) --ix;
    while (ix < NX - 2 && sg[ix + 1] < x) ++ix;
    return ix;
}

__device__ __forceinline__ float interp(float x, float y, int ix, int iy,
                                        const float4 q,
                                        const float* __restrict__ sgx,
                                        const float* __restrict__ sgy) {
    float xi = sgx[ix], xi1 = sgx[ix + 1];
    float yi = sgy[iy], yi1 = sgy[iy + 1];
    float rdx = 1.0f / fmaxf(xi1 - xi, EPSV);
    float rdy = 1.0f / fmaxf(yi1 - yi, EPSV);
    float n1x = (xi1 - x) * rdx;
    float n2x = (x - xi) * rdx;
    float n1y = (yi1 - y) * rdy;
    float n2y = (y - yi) * rdy;
    return n1y * (n1x * q.x + n2x * q.y) + n2y * (n1x * q.z + n2x * q.w);
}

__global__ __launch_bounds__(BLOCK_T)
void eval_kernel(const float4* __restrict__ xe4, float4* __restrict__ out4,
                 const float2* __restrict__ xe2, float* __restrict__ outs,
                 int n) {
    __shared__ float sgx[NX];
    __shared__ float sgy[NY];
    for (int i = threadIdx.x; i < NX; i += BLOCK_T) sgx[i] = g_gx[i];
    for (int i = threadIdx.x; i < NY; i += BLOCK_T) sgy[i] = g_gy[i];
    __syncthreads();

    int gid = blockIdx.x * BLOCK_T + threadIdx.x;
    int p0  = gid * PTS_PER_THREAD;

    if (p0 + PTS_PER_THREAD <= n) {
        // fast path: 8 points, processed as two groups of 4
        #pragma unroll
        for (int grp = 0; grp < 2; grp++) {
            // 2 float4 loads = 4 points (x,y interleaved)
            float4 a = __ldcs(&xe4[gid * 4 + grp * 2 + 0]);
            float4 b = __ldcs(&xe4[gid * 4 + grp * 2 + 1]);
            float px[4] = {a.x, a.z, b.x, b.z};
            float py[4] = {a.y, a.w, b.y, b.w};

            int ix[4], iy[4];
            #pragma unroll
            for (int k = 0; k < 4; k++) {
                ix[k] = find_cell(px[k], sgx);
                iy[k] = find_cell(py[k], sgy);
            }
            // issue all 4 gathers before consuming any (MLP)
            float4 q[4];
            #pragma unroll
            for (int k = 0; k < 4; k++)
                q[k] = __ldg(&g_quad[(ix[k] << 10) + iy[k]]);

            float4 r;
            r.x = interp(px[0], py[0], ix[0], iy[0], q[0], sgx, sgy);
            r.y = interp(px[1], py[1], ix[1], iy[1], q[1], sgx, sgy);
            r.z = interp(px[2], py[2], ix[2], iy[2], q[2], sgx, sgy);
            r.w = interp(px[3], py[3], ix[3], iy[3], q[3], sgx, sgy);
            __stcs(&out4[gid * 2 + grp], r);
        }
    } else {
        // tail: scalar
        for (int i = p0; i < n; i++) {
            float2 p = xe2[i];
            int ix = find_cell(p.x, sgx);
            int iy = find_cell(p.y, sgy);
            float4 q = __ldg(&g_quad[(ix << 10) + iy]);
            outs[i] = interp(p.x, p.y, ix, iy, q, sgx, sgy);
        }
    }
}

// ---------------------------------------------------------------------------
extern "C" void kernel_launch(void* const* d_in, const int* in_sizes, int n_in,
                              void* d_out, int out_size) {
    const float* xe   = (const float*)d_in[0];    // x_eval (N,2) f32
    const float* incx = (const float*)d_in[1];    // increments_x (1023)
    const float* incy = (const float*)d_in[2];    // increments_y (1023)
    const float* u    = (const float*)d_in[3];    // u (1024,1024)
    int n = out_size;                             // 8,000,000

    build_all<<<(NX - 1) + 2, BLOCK_T>>>(incx, incy, u);

    int threads_needed = (n + PTS_PER_THREAD - 1) / PTS_PER_THREAD;
    int blocks = (threads_needed + BLOCK_T - 1) / BLOCK_T;
    eval_kernel<<<blocks, BLOCK_T>>>((const float4*)xe, (float4*)d_out,
                                     (const float2*)xe, (float*)d_out, n);
}

// round 3
// speedup vs baseline: 1.2343x; 1.2343x over previous
#include <cuda_runtime.h>
#include <cuda_bf16.h>

#define NX 1024
#define NCELL 1023
#define EPSV 1e-10f
#define BLOCK_T 256
#define PTS_PER_THREAD 8

// Scratch (__device__ globals — allocation-free rule)
__device__ float2 g_cellx[NCELL];           // (x_i, 1/max(dx,EPS)) per cell
__device__ float2 g_celly[NCELL];
__device__ float4 g_quad[(NX - 1) * NX];    // {u00,u10,u01,u11} per cell (ix<<10 | iy)

// ---------------------------------------------------------------------------
// Builder: blocks 0..1022 pack quad rows; blocks 1023/1024 build the x/y
// adaptive grids (shfl scan) and emit the per-cell (x_i, rdx) tables.
// ---------------------------------------------------------------------------
__device__ __forceinline__ void build_one_grid(const float* __restrict__ inc,
                                               float2* __restrict__ cells) {
    __shared__ float scum[1024];
    __shared__ float sg[1024];
    __shared__ float swarp[8];

    const int t    = threadIdx.x;       // 0..255
    const int lane = t & 31;
    const int warp = t >> 5;

    float v[4];
    #pragma unroll
    for (int j = 0; j < 4; j++) {
        int idx = 4 * t + j;
        float val = 0.0f;
        if (idx < 1023) {
            float xv = inc[idx];
            float sp = fmaxf(xv, 0.0f) + log1pf(expf(-fabsf(xv)));  // softplus
            val = fmaxf(sp, 1e-6f);
        }
        v[j] = val;
    }
    float c0 = v[0];
    float c1 = c0 + v[1];
    float c2 = c1 + v[2];
    float c3 = c2 + v[3];

    float incl = c3;
    #pragma unroll
    for (int off = 1; off < 32; off <<= 1) {
        float up = __shfl_up_sync(0xffffffff, incl, off);
        if (lane >= off) incl += up;
    }
    float thr_excl = incl - c3;
    if (lane == 31) swarp[warp] = incl;
    __syncthreads();

    if (warp == 0 && lane < 8) {
        float w = swarp[lane];
        #pragma unroll
        for (int off = 1; off < 8; off <<= 1) {
            float up = __shfl_up_sync(0xff, w, off);
            if (lane >= off) w += up;
        }
        swarp[lane] = w - swarp[lane];
    }
    __syncthreads();

    float pref = swarp[warp] + thr_excl;
    scum[4 * t + 0] = pref + c0;
    scum[4 * t + 1] = pref + c1;
    scum[4 * t + 2] = pref + c2;
    scum[4 * t + 3] = pref + c3;
    __syncthreads();

    float total = scum[1022];
    if (t == 0) sg[0] = 0.0f;
    #pragma unroll
    for (int j = 0; j < 4; j++) {
        int idx = 4 * t + j;
        if (idx < 1022)       sg[idx + 1] = scum[idx] / total;
        else if (idx == 1022) sg[1023]    = 1.0f;
    }
    __syncthreads();

    // emit per-cell (x_i, rdx)
    #pragma unroll
    for (int j = 0; j < 4; j++) {
        int idx = 4 * t + j;
        if (idx < NCELL) {
            float xi  = sg[idx];
            float rdx = 1.0f / fmaxf(sg[idx + 1] - xi, EPSV);
            cells[idx] = make_float2(xi, rdx);
        }
    }
}

__global__ __launch_bounds__(BLOCK_T)
void build_all(const float* __restrict__ incx,
               const float* __restrict__ incy,
               const float* __restrict__ u) {
    int bx = blockIdx.x;
    if (bx < NX - 1) {
        const float* r0 = u + bx * NX;
        const float* r1 = r0 + NX;
        float4* qrow = g_quad + (bx << 10);
        for (int iy = threadIdx.x; iy < NX - 1; iy += BLOCK_T) {
            float4 q;
            q.x = r0[iy];
            q.y = r1[iy];
            q.z = r0[iy + 1];
            q.w = r1[iy + 1];
            qrow[iy] = q;
        }
    } else if (bx == NX - 1) {
        build_one_grid(incx, g_cellx);
    } else {
        build_one_grid(incy, g_celly);
    }
}

// ---------------------------------------------------------------------------
// Eval: one LDS.64 per dim gives cell membership AND the weights.
// ---------------------------------------------------------------------------
__device__ __forceinline__ int locate(float x, const float2* __restrict__ sc,
                                      float& t) {
    int i = min(max(__float2int_rd(x * 1023.0f), 0), NCELL - 1);
    float2 c = sc[i];
    t = (x - c.x) * c.y;
    while (t < 0.0f && i > 0)            { c = sc[--i]; t = (x - c.x) * c.y; }
    while (t >= 1.0f && i < NCELL - 1)   { c = sc[++i]; t = (x - c.x) * c.y; }
    return i;
}

__device__ __forceinline__ float blend(float tx, float ty, float4 q) {
    // (1-ty)*((1-tx)*u00 + tx*u10) + ty*((1-tx)*u01 + tx*u11)  (lerp form)
    float a = fmaf(tx, q.y - q.x, q.x);
    float b = fmaf(tx, q.w - q.z, q.z);
    return fmaf(ty, b - a, a);
}

__global__ __launch_bounds__(BLOCK_T)
void eval_kernel(const float4* __restrict__ xe4, float4* __restrict__ out4,
                 const float2* __restrict__ xe2, float* __restrict__ outs,
                 int n) {
    __shared__ float2 scx[NCELL];
    __shared__ float2 scy[NCELL];
    for (int i = threadIdx.x; i < NCELL; i += BLOCK_T) {
        scx[i] = g_cellx[i];
        scy[i] = g_celly[i];
    }
    __syncthreads();

    int gid = blockIdx.x * BLOCK_T + threadIdx.x;
    int p0  = gid * PTS_PER_THREAD;

    if (p0 + PTS_PER_THREAD <= n) {
        #pragma unroll
        for (int grp = 0; grp < 2; grp++) {
            float4 a = __ldcs(&xe4[gid * 4 + grp * 2 + 0]);
            float4 b = __ldcs(&xe4[gid * 4 + grp * 2 + 1]);
            float px[4] = {a.x, a.z, b.x, b.z};
            float py[4] = {a.y, a.w, b.y, b.w};

            int ix[4], iy[4];
            float tx[4], ty[4];
            #pragma unroll
            for (int k = 0; k < 4; k++) {
                ix[k] = locate(px[k], scx, tx[k]);
                iy[k] = locate(py[k], scy, ty[k]);
            }
            float4 q[4];
            #pragma unroll
            for (int k = 0; k < 4; k++)
                q[k] = __ldg(&g_quad[(ix[k] << 10) + iy[k]]);

            float4 r;
            r.x = blend(tx[0], ty[0], q[0]);
            r.y = blend(tx[1], ty[1], q[1]);
            r.z = blend(tx[2], ty[2], q[2]);
            r.w = blend(tx[3], ty[3], q[3]);
            __stcs(&out4[gid * 2 + grp], r);
        }
    } else {
        for (int i = p0; i < n; i++) {
            float2 p = xe2[i];
            float tx, ty;
            int ix = locate(p.x, scx, tx);
            int iy = locate(p.y, scy, ty);
            float4 q = __ldg(&g_quad[(ix << 10) + iy]);
            outs[i] = blend(tx, ty, q);
        }
    }
}

// ---------------------------------------------------------------------------
extern "C" void kernel_launch(void* const* d_in, const int* in_sizes, int n_in,
                              void* d_out, int out_size) {
    const float* xe   = (const float*)d_in[0];
    const float* incx = (const float*)d_in[1];
    const float* incy = (const float*)d_in[2];
    const float* u    = (const float*)d_in[3];
    int n = out_size;   // 8,000,000

    build_all<<<(NX - 1) + 2, BLOCK_T>>>(incx, incy, u);

    int threads_needed = (n + PTS_PER_THREAD - 1) / PTS_PER_THREAD;
    int blocks = (threads_needed + BLOCK_T - 1) / BLOCK_T;
    eval_kernel<<<blocks, BLOCK_T>>>((const float4*)xe, (float4*)d_out,
                                     (const float2*)xe, (float*)d_out, n);
}